// round 14
// baseline (speedup 1.0000x reference)
#include <cuda_runtime.h>
#include <math.h>

#define E_N 500000
#define G_N 256
#define H_N 256
#define H2_N 512
#define EPS_F 1.1920929e-07f
#define LOG_EPS -15.942385f
#define SEG_CAP 2560

// ---------------- scratch (device globals; no allocation allowed) ------------
__device__ float d_v_edge[H_N];          // att_vec @ W_edge
__device__ float d_v_query[H_N];         // att_vec @ W_query (kept for clarity)
__device__ float d_q_att[G_N];           // question · v_query per graph
__device__ float d_att_raw[E_N];         // post-leaky/bonus attention logits
__device__ float d_sum_tok[G_N * H_N];   // segment sums of raw edge tokens
__device__ int   d_seg[G_N + 1];         // segment bounds (sorted edge_batch)
__device__ float d_WeT[H_N * H_N];       // W_edge^T
__device__ float d_W1T[H2_N * H_N];      // W1^T

__device__ __forceinline__ float warp_sum(float v) {
    #pragma unroll
    for (int o = 16; o; o >>= 1) v += __shfl_xor_sync(0xffffffffu, v, o);
    return v;
}
__device__ __forceinline__ float warp_max(float v) {
    #pragma unroll
    for (int o = 16; o; o >>= 1) v = fmaxf(v, __shfl_xor_sync(0xffffffffu, v, o));
    return v;
}

// ---------------- kAB: all prep in one launch --------------------------------
// grid 320 x 256 thr:
//   b 0-7: v_edge   b 8-15: v_query   b 16-31: zero sum_tok
//   b 32-95: W_edge^T   b 96-223: W1^T
//   b 224-255: q_att (8 graphs/block; recomputes v_query LOCALLY -> no race)
//   b 256-319: segment bounds
__global__ void kAB_prep(const float* __restrict__ W_edge,
                         const float* __restrict__ W_query,
                         const float* __restrict__ W1,
                         const float* __restrict__ att_vec,
                         const float* __restrict__ q,
                         const int* __restrict__ batch) {
    int b = blockIdx.x;
    int tid = threadIdx.x;
    int tx = tid & 31, ty = tid >> 5;      // 32 x 8
    if (b < 16) {
        const float* W = (b < 8) ? W_edge : W_query;
        float* v       = (b < 8) ? d_v_edge : d_v_query;
        int bx = b & 7;
        __shared__ float a[H_N];
        __shared__ float part[8][32];
        a[tid] = att_vec[tid];
        __syncthreads();
        int t0 = bx * 32 + tx;
        float s = 0.f;
        #pragma unroll 8
        for (int j = ty * 32; j < ty * 32 + 32; ++j)
            s = fmaf(a[j], W[j * H_N + t0], s);
        part[ty][tx] = s;
        __syncthreads();
        if (ty == 0) {
            float r = part[0][tx] + part[1][tx] + part[2][tx] + part[3][tx]
                    + part[4][tx] + part[5][tx] + part[6][tx] + part[7][tx];
            v[t0] = r;
        }
    } else if (b < 32) {
        int idx = (b - 16) * 256 + tid;
        for (int i = idx; i < G_N * H_N; i += 16 * 256) d_sum_tok[i] = 0.0f;
    } else if (b < 96) {
        int tile = b - 32;                  // 8x8 tiles over 256x256
        int ti = tile >> 3, tj = tile & 7;
        __shared__ float t[32][33];
        #pragma unroll
        for (int r = 0; r < 4; ++r)
            t[ty * 4 + r][tx] = W_edge[(ti * 32 + ty * 4 + r) * H_N + tj * 32 + tx];
        __syncthreads();
        #pragma unroll
        for (int r = 0; r < 4; ++r)
            d_WeT[(tj * 32 + ty * 4 + r) * H_N + ti * 32 + tx] = t[tx][ty * 4 + r];
    } else if (b < 224) {
        int tile = b - 96;                  // W1: 256x512 -> 8 x 16 tiles
        int ti = tile >> 4, tj = tile & 15;
        __shared__ float t[32][33];
        #pragma unroll
        for (int r = 0; r < 4; ++r)
            t[ty * 4 + r][tx] = W1[(ti * 32 + ty * 4 + r) * H2_N + tj * 32 + tx];
        __syncthreads();
        #pragma unroll
        for (int r = 0; r < 4; ++r)
            d_W1T[(tj * 32 + ty * 4 + r) * H_N + ti * 32 + tx] = t[tx][ty * 4 + r];
    } else if (b < 256) {
        // q_att role: recompute v_query into smem locally (avoids cross-block
        // race on d_v_query within this launch), then 8 graph dots.
        __shared__ float a[H_N];
        __shared__ float vq[H_N];
        a[tid] = att_vec[tid];
        __syncthreads();
        float s = 0.f;
        #pragma unroll 8
        for (int j = 0; j < H_N; ++j)
            s = fmaf(a[j], W_query[j * H_N + tid], s);
        vq[tid] = s;
        __syncthreads();

        int w = (b - 224) * 8 + ty;         // graph index
        const float4* q4 = (const float4*)(q + (size_t)w * H_N);
        const float4* v4 = (const float4*)vq;
        float d = 0.f;
        #pragma unroll
        for (int k = 0; k < 2; ++k) {
            float4 t = q4[tx + 32 * k];
            float4 v = v4[tx + 32 * k];
            d += t.x * v.x + t.y * v.y + t.z * v.z + t.w * v.w;
        }
        d = warp_sum(d);
        if (tx == 0) d_q_att[w] = d;
    } else {
        int idx = (b - 256) * 256 + tid;
        int stride = 64 * 256;
        for (int e = idx; e < E_N; e += stride) {
            int bc = batch[e];
            int bp = (e == 0) ? -1 : batch[e - 1];
            for (int g = bp + 1; g <= bc; ++g) d_seg[g] = e;
            if (e == E_N - 1)
                for (int g = bc + 1; g <= G_N; ++g) d_seg[g] = E_N;
        }
    }
}

// ---------------- K3: dominant streaming pass, depth-2 prefetch --------------
#define K3_BLOCK 256
#define K3_GRID  592
#define K3_WARPS (K3_GRID * (K3_BLOCK / 32))

__global__ __launch_bounds__(K3_BLOCK) void k3_edges(
        const float* __restrict__ tok,
        const int* __restrict__ batch,
        const int* __restrict__ sel) {
    int warp = (blockIdx.x * blockDim.x + threadIdx.x) >> 5;
    int lane = threadIdx.x & 31;
    const int chunk = (E_N + K3_WARPS - 1) / K3_WARPS;
    int e0 = warp * chunk;
    int e1 = min(e0 + chunk, E_N);
    if (e0 >= e1) return;

    float4 v0 = ((const float4*)d_v_edge)[lane];
    float4 v1 = ((const float4*)d_v_edge)[lane + 32];

    float4 a0 = make_float4(0.f, 0.f, 0.f, 0.f);
    float4 a1 = make_float4(0.f, 0.f, 0.f, 0.f);
    float keep = 0.f;

    const float4* base = (const float4*)tok;
    float4 t0 = __ldcs(base + (size_t)e0 * 64 + lane);
    float4 t1 = __ldcs(base + (size_t)e0 * 64 + 32 + lane);
    int gt = batch[e0];
    float4 u0 = t0, u1 = t1;
    int gu = gt;
    if (e0 + 1 < e1) {
        u0 = __ldcs(base + (size_t)(e0 + 1) * 64 + lane);
        u1 = __ldcs(base + (size_t)(e0 + 1) * 64 + 32 + lane);
        gu = batch[e0 + 1];
    }
    int cg = gt;

    for (int e = e0; e < e1; ++e) {
        float4 p0 = u0, p1 = u1; int gp = gu;
        if (e + 2 < e1) {
            p0 = __ldcs(base + (size_t)(e + 2) * 64 + lane);
            p1 = __ldcs(base + (size_t)(e + 2) * 64 + 32 + lane);
            gp = batch[e + 2];
        }
        if (gt != cg) {  // segment boundary: flush partial sums
            float* dst = d_sum_tok + (size_t)cg * H_N;
            atomicAdd(&dst[4 * lane + 0], a0.x);
            atomicAdd(&dst[4 * lane + 1], a0.y);
            atomicAdd(&dst[4 * lane + 2], a0.z);
            atomicAdd(&dst[4 * lane + 3], a0.w);
            atomicAdd(&dst[128 + 4 * lane + 0], a1.x);
            atomicAdd(&dst[128 + 4 * lane + 1], a1.y);
            atomicAdd(&dst[128 + 4 * lane + 2], a1.z);
            atomicAdd(&dst[128 + 4 * lane + 3], a1.w);
            a0 = make_float4(0.f, 0.f, 0.f, 0.f);
            a1 = make_float4(0.f, 0.f, 0.f, 0.f);
            cg = gt;
        }
        a0.x += t0.x; a0.y += t0.y; a0.z += t0.z; a0.w += t0.w;
        a1.x += t1.x; a1.y += t1.y; a1.z += t1.z; a1.w += t1.w;

        float d = t0.x * v0.x;
        d = fmaf(t0.y, v0.y, d); d = fmaf(t0.z, v0.z, d); d = fmaf(t0.w, v0.w, d);
        d = fmaf(t1.x, v1.x, d); d = fmaf(t1.y, v1.y, d);
        d = fmaf(t1.z, v1.z, d); d = fmaf(t1.w, v1.w, d);
        float tot = warp_sum(d);

        float att = tot + d_q_att[gt];
        att = att > 0.f ? att : 0.2f * att;             // LeakyReLU(0.2)
        if (sel[e] == 0) att += 0.5f;                   // frontier bonus
        if (lane == (e & 31)) keep = att;

        if ((e & 31) == 31 || e == e1 - 1) {            // coalesced 128B store
            int bse = e & ~31;
            int idx = bse + lane;
            if (idx >= e0 && idx <= e)
                d_att_raw[idx] = keep;
        }

        t0 = u0; t1 = u1; gt = gu;
        u0 = p0; u1 = p1; gu = gp;
    }
    float* dst = d_sum_tok + (size_t)cg * H_N;
    atomicAdd(&dst[4 * lane + 0], a0.x);
    atomicAdd(&dst[4 * lane + 1], a0.y);
    atomicAdd(&dst[4 * lane + 2], a0.z);
    atomicAdd(&dst[4 * lane + 3], a0.w);
    atomicAdd(&dst[128 + 4 * lane + 0], a1.x);
    atomicAdd(&dst[128 + 4 * lane + 1], a1.y);
    atomicAdd(&dst[128 + 4 * lane + 2], a1.z);
    atomicAdd(&dst[128 + 4 * lane + 3], a1.w);
}

// ---------------- K_TAIL: softmax role + (pool GEMM + LN + MLP + stop) role --
// grid 320 x 512 thr: blocks 0-255 -> softmax/logits; 256-319 -> 4 graphs each.
__global__ __launch_bounds__(512) void k_tail(
        const int* __restrict__ sel,
        const float* __restrict__ q,
        const float* __restrict__ ln_g,
        const float* __restrict__ ln_b,
        const float* __restrict__ b1,
        const float* __restrict__ W2,
        const float* __restrict__ b2,
        float* __restrict__ out_edge,
        float* __restrict__ out_pool,
        float* __restrict__ out_stop) {
    int tid = threadIdx.x;
    int lane = tid & 31, wid = tid >> 5;   // 16 warps

    if (blockIdx.x < 256) {
        // ================= role A: segment softmax + edge logits =============
        int gi = blockIdx.x;
        int start = d_seg[gi], end = d_seg[gi + 1];
        int n = end - start;

        __shared__ float wred[16];
        __shared__ float bcast;
        __shared__ float satt[SEG_CAP];
        __shared__ unsigned char smsk[SEG_CAP];

        if (n <= SEG_CAP) {
            #pragma unroll 4
            for (int i = tid; i < n; i += 512) {
                satt[i] = d_att_raw[start + i];
                smsk[i] = (unsigned char)(sel[start + i] != 0);
            }
            __syncthreads();

            float mx = -INFINITY;
            #pragma unroll 4
            for (int i = tid; i < n; i += 512) mx = fmaxf(mx, satt[i]);
            mx = warp_max(mx);
            if (lane == 0) wred[wid] = mx;
            __syncthreads();
            if (wid == 0) {
                float v = (lane < 16) ? wred[lane] : -INFINITY;
                v = warp_max(v);
                if (lane == 0) bcast = v;
            }
            __syncthreads();
            mx = bcast;

            float sm = 0.f;
            #pragma unroll 4
            for (int i = tid; i < n; i += 512)
                if (!smsk[i]) sm += expf(satt[i] - mx);
            sm = warp_sum(sm);
            if (lane == 0) wred[wid] = sm;
            __syncthreads();
            if (wid == 0) {
                float v = (lane < 16) ? wred[lane] : 0.f;
                v = warp_sum(v);
                if (lane == 0) bcast = mx + logf(fmaxf(v, EPS_F));
            }
            __syncthreads();
            float sub = bcast;

            #pragma unroll 4
            for (int i = tid; i < n; i += 512) {
                float v = LOG_EPS;
                if (!smsk[i]) v = fmaxf(satt[i] - sub, LOG_EPS);
                out_edge[start + i] = v;
            }
        } else {
            float mx = -INFINITY;
            for (int e = start + tid; e < end; e += 512) mx = fmaxf(mx, d_att_raw[e]);
            mx = warp_max(mx);
            if (lane == 0) wred[wid] = mx;
            __syncthreads();
            if (wid == 0) {
                float v = (lane < 16) ? wred[lane] : -INFINITY;
                v = warp_max(v);
                if (lane == 0) bcast = v;
            }
            __syncthreads();
            mx = bcast;

            float sm = 0.f;
            for (int e = start + tid; e < end; e += 512)
                if (sel[e] == 0) sm += expf(d_att_raw[e] - mx);
            sm = warp_sum(sm);
            if (lane == 0) wred[wid] = sm;
            __syncthreads();
            if (wid == 0) {
                float v = (lane < 16) ? wred[lane] : 0.f;
                v = warp_sum(v);
                if (lane == 0) bcast = mx + logf(fmaxf(v, EPS_F));
            }
            __syncthreads();
            float sub = bcast;

            for (int e = start + tid; e < end; e += 512) {
                float v = LOG_EPS;
                if (sel[e] == 0) v = fmaxf(d_att_raw[e] - sub, LOG_EPS);
                out_edge[e] = v;
            }
        }
    } else {
        // ============ role B: 4 graphs: pool GEMM + LN + MLP + stop ==========
        int rb = blockIdx.x - 256;          // 0..63
        int g0 = rb * 4;
        int j = tid & 255, kh = tid >> 8;   // kh in {0,1}

        __shared__ float stok[4][H_N];      // 4 KB
        __shared__ float spart[2][4][H_N];  // 8 KB (GEMM partials)
        __shared__ float sxn[4][H2_N];      // 8 KB
        __shared__ float sred[16];
        __shared__ float bc[2];

        // load 4 sum_tok rows
        #pragma unroll
        for (int i = tid; i < 4 * H_N; i += 512)
            stok[i >> 8][i & 255] = d_sum_tok[(size_t)g0 * H_N + i];
        __syncthreads();

        // ---- GEMM1: pooled partials, k-split across kh ----
        {
            float ac0 = 0.f, ac1 = 0.f, ac2 = 0.f, ac3 = 0.f;
            int kb = kh * 128;
            #pragma unroll 8
            for (int k = kb; k < kb + 128; ++k) {
                float w = d_WeT[k * H_N + j];
                ac0 = fmaf(stok[0][k], w, ac0);
                ac1 = fmaf(stok[1][k], w, ac1);
                ac2 = fmaf(stok[2][k], w, ac2);
                ac3 = fmaf(stok[3][k], w, ac3);
            }
            spart[kh][0][j] = ac0;
            spart[kh][1][j] = ac1;
            spart[kh][2][j] = ac2;
            spart[kh][3][j] = ac3;
        }
        __syncthreads();

        // ---- per-graph: pooled, LayerNorm -> sxn ----
        #pragma unroll
        for (int gg = 0; gg < 4; ++gg) {
            int g = g0 + gg;
            float invden = 1.0f / (float)max(d_seg[g + 1] - d_seg[g], 1);
            float pooled = (spart[0][gg][j] + spart[1][gg][j]) * invden;
            float x1 = q[(size_t)g * H_N + j];

            // kh==0 warps reduce sum, kh==1 warps reduce sumsq (same j range)
            float v = kh ? (pooled * pooled + x1 * x1) : (pooled + x1);
            v = warp_sum(v);
            if (lane == 0) sred[wid] = v;
            __syncthreads();
            if (wid == 0) {
                float t = (lane < 8) ? sred[lane] : 0.f;
                t = warp_sum(t);
                if (lane == 0) bc[0] = t * (1.0f / 512.0f);
            }
            if (wid == 1) {
                float t = (lane < 8) ? sred[8 + lane] : 0.f;
                t = warp_sum(t);
                if (lane == 0) bc[1] = t * (1.0f / 512.0f);
            }
            __syncthreads();
            float mu = bc[0];
            float var = bc[1] - mu * mu;
            float inv = rsqrtf(var + 1e-5f);
            if (kh == 0) {
                sxn[gg][j] = (pooled - mu) * inv * ln_g[j] + ln_b[j];
                out_pool[(size_t)g * H_N + j] = pooled;
            } else {
                sxn[gg][256 + j] = (x1 - mu) * inv * ln_g[256 + j] + ln_b[256 + j];
            }
            __syncthreads();
        }

        // ---- GEMM2: h1 partials, k-split across kh (K=512) ----
        {
            float ac0 = 0.f, ac1 = 0.f, ac2 = 0.f, ac3 = 0.f;
            int kb = kh * 256;
            #pragma unroll 8
            for (int k = kb; k < kb + 256; ++k) {
                float w = d_W1T[k * H_N + j];
                ac0 = fmaf(sxn[0][k], w, ac0);
                ac1 = fmaf(sxn[1][k], w, ac1);
                ac2 = fmaf(sxn[2][k], w, ac2);
                ac3 = fmaf(sxn[3][k], w, ac3);
            }
            spart[kh][0][j] = ac0;
            spart[kh][1][j] = ac1;
            spart[kh][2][j] = ac2;
            spart[kh][3][j] = ac3;
        }
        __syncthreads();

        // ---- per-graph: GELU + stop dot ----
        #pragma unroll
        for (int gg = 0; gg < 4; ++gg) {
            int g = g0 + gg;
            float x = spart[0][gg][j] + spart[1][gg][j] + b1[j];
            float h = 0.5f * x * (1.0f + erff(x * 0.70710678118654752f));
            float v = kh ? 0.f : h * W2[j];
            v = warp_sum(v);
            if (lane == 0) sred[wid] = v;
            __syncthreads();
            if (wid == 0) {
                float t = (lane < 8) ? sred[lane] : 0.f;
                t = warp_sum(t);
                if (lane == 0) out_stop[g] = t + b2[0];
            }
            __syncthreads();
        }
    }
}

// ---------------- launch -----------------------------------------------------
extern "C" void kernel_launch(void* const* d_in, const int* in_sizes, int n_in,
                              void* d_out, int out_size) {
    const float* edge_tokens     = (const float*)d_in[0];
    const float* question_tokens = (const float*)d_in[1];
    const int*   edge_batch      = (const int*)d_in[2];
    const int*   selected_mask   = (const int*)d_in[3];   // bool promoted to int32
    const float* W_edge          = (const float*)d_in[4];
    const float* W_query         = (const float*)d_in[5];
    const float* att_vec         = (const float*)d_in[6];
    const float* ln_g            = (const float*)d_in[7];
    const float* ln_b            = (const float*)d_in[8];
    const float* W1              = (const float*)d_in[9];
    const float* b1              = (const float*)d_in[10];
    const float* W2              = (const float*)d_in[11];
    const float* b2              = (const float*)d_in[12];

    float* out         = (float*)d_out;
    float* out_edge    = out;                 // [E]
    float* out_stop    = out + E_N;           // [G]
    float* out_pooled  = out + E_N + G_N;     // [G, H]

    kAB_prep<<<320, 256>>>(W_edge, W_query, W1, att_vec,
                           question_tokens, edge_batch);
    k3_edges<<<K3_GRID, K3_BLOCK>>>(edge_tokens, edge_batch, selected_mask);
    k_tail<<<320, 512>>>(selected_mask, question_tokens, ln_g, ln_b,
                         b1, W2, b2, out_edge, out_pooled, out_stop);
}

// round 15
// speedup vs baseline: 1.0198x; 1.0198x over previous
#include <cuda_runtime.h>
#include <math.h>

#define E_N 500000
#define G_N 256
#define H_N 256
#define H2_N 512
#define EPS_F 1.1920929e-07f
#define LOG_EPS -15.942385f
#define SEG_CAP 2560

// ---------------- scratch (device globals; no allocation allowed) ------------
__device__ float d_v_edge[H_N];          // att_vec @ W_edge
__device__ float d_v_query[H_N];         // att_vec @ W_query (unused by later kernels)
__device__ float d_q_att[G_N];           // question · v_query per graph
__device__ float d_att_raw[E_N];         // post-leaky/bonus attention logits
__device__ float d_sum_tok[G_N * H_N];   // segment sums of raw edge tokens
__device__ int   d_seg[G_N + 1];         // segment bounds (sorted edge_batch)
__device__ float d_WeT[H_N * H_N];       // W_edge^T
__device__ float d_W1T[H2_N * H_N];      // W1^T

__device__ __forceinline__ float warp_sum(float v) {
    #pragma unroll
    for (int o = 16; o; o >>= 1) v += __shfl_xor_sync(0xffffffffu, v, o);
    return v;
}
__device__ __forceinline__ float warp_max(float v) {
    #pragma unroll
    for (int o = 16; o; o >>= 1) v = fmaxf(v, __shfl_xor_sync(0xffffffffu, v, o));
    return v;
}

// ---------------- kAB: all prep in one launch --------------------------------
// grid 320 x 256 thr:
//   b 0-7: v_edge   b 8-15: v_query   b 16-31: zero sum_tok
//   b 32-95: W_edge^T   b 96-223: W1^T
//   b 224-255: q_att (8 graphs/block; warp-parallel LOCAL v_query recompute)
//   b 256-319: segment bounds
__global__ void kAB_prep(const float* __restrict__ W_edge,
                         const float* __restrict__ W_query,
                         const float* __restrict__ W1,
                         const float* __restrict__ att_vec,
                         const float* __restrict__ q,
                         const int* __restrict__ batch) {
    int b = blockIdx.x;
    int tid = threadIdx.x;
    int tx = tid & 31, ty = tid >> 5;      // 32 x 8
    if (b < 16) {
        const float* W = (b < 8) ? W_edge : W_query;
        float* v       = (b < 8) ? d_v_edge : d_v_query;
        int bx = b & 7;
        __shared__ float a[H_N];
        __shared__ float part[8][32];
        a[tid] = att_vec[tid];
        __syncthreads();
        int t0 = bx * 32 + tx;
        float s = 0.f;
        #pragma unroll 8
        for (int j = ty * 32; j < ty * 32 + 32; ++j)
            s = fmaf(a[j], W[j * H_N + t0], s);
        part[ty][tx] = s;
        __syncthreads();
        if (ty == 0) {
            float r = part[0][tx] + part[1][tx] + part[2][tx] + part[3][tx]
                    + part[4][tx] + part[5][tx] + part[6][tx] + part[7][tx];
            v[t0] = r;
        }
    } else if (b < 32) {
        int idx = (b - 16) * 256 + tid;
        for (int i = idx; i < G_N * H_N; i += 16 * 256) d_sum_tok[i] = 0.0f;
    } else if (b < 96) {
        int tile = b - 32;                  // 8x8 tiles over 256x256
        int ti = tile >> 3, tj = tile & 7;
        __shared__ float t[32][33];
        #pragma unroll
        for (int r = 0; r < 4; ++r)
            t[ty * 4 + r][tx] = W_edge[(ti * 32 + ty * 4 + r) * H_N + tj * 32 + tx];
        __syncthreads();
        #pragma unroll
        for (int r = 0; r < 4; ++r)
            d_WeT[(tj * 32 + ty * 4 + r) * H_N + ti * 32 + tx] = t[tx][ty * 4 + r];
    } else if (b < 224) {
        int tile = b - 96;                  // W1: 256x512 -> 8 x 16 tiles
        int ti = tile >> 4, tj = tile & 15;
        __shared__ float t[32][33];
        #pragma unroll
        for (int r = 0; r < 4; ++r)
            t[ty * 4 + r][tx] = W1[(ti * 32 + ty * 4 + r) * H2_N + tj * 32 + tx];
        __syncthreads();
        #pragma unroll
        for (int r = 0; r < 4; ++r)
            d_W1T[(tj * 32 + ty * 4 + r) * H_N + ti * 32 + tx] = t[tx][ty * 4 + r];
    } else if (b < 256) {
        // q_att role: warp-parallel local v_query recompute (8 independent
        // accumulator chains/lane, coalesced), then 8 graph dots.
        __shared__ float a[H_N];
        __shared__ float part[8][H_N];
        __shared__ float vq[H_N];
        a[tid] = att_vec[tid];
        __syncthreads();

        float acc0 = 0.f, acc1 = 0.f, acc2 = 0.f, acc3 = 0.f;
        float acc4 = 0.f, acc5 = 0.f, acc6 = 0.f, acc7 = 0.f;
        #pragma unroll 4
        for (int jj = 0; jj < 32; ++jj) {
            int j = ty * 32 + jj;
            float aj = a[j];
            const float* row = W_query + j * H_N;
            acc0 = fmaf(aj, row[0 * 32 + tx], acc0);
            acc1 = fmaf(aj, row[1 * 32 + tx], acc1);
            acc2 = fmaf(aj, row[2 * 32 + tx], acc2);
            acc3 = fmaf(aj, row[3 * 32 + tx], acc3);
            acc4 = fmaf(aj, row[4 * 32 + tx], acc4);
            acc5 = fmaf(aj, row[5 * 32 + tx], acc5);
            acc6 = fmaf(aj, row[6 * 32 + tx], acc6);
            acc7 = fmaf(aj, row[7 * 32 + tx], acc7);
        }
        part[ty][0 * 32 + tx] = acc0;
        part[ty][1 * 32 + tx] = acc1;
        part[ty][2 * 32 + tx] = acc2;
        part[ty][3 * 32 + tx] = acc3;
        part[ty][4 * 32 + tx] = acc4;
        part[ty][5 * 32 + tx] = acc5;
        part[ty][6 * 32 + tx] = acc6;
        part[ty][7 * 32 + tx] = acc7;
        __syncthreads();
        vq[tid] = part[0][tid] + part[1][tid] + part[2][tid] + part[3][tid]
                + part[4][tid] + part[5][tid] + part[6][tid] + part[7][tid];
        __syncthreads();

        int w = (b - 224) * 8 + ty;         // graph index
        const float4* q4 = (const float4*)(q + (size_t)w * H_N);
        const float4* v4 = (const float4*)vq;
        float d = 0.f;
        #pragma unroll
        for (int k = 0; k < 2; ++k) {
            float4 t = q4[tx + 32 * k];
            float4 v = v4[tx + 32 * k];
            d += t.x * v.x + t.y * v.y + t.z * v.z + t.w * v.w;
        }
        d = warp_sum(d);
        if (tx == 0) d_q_att[w] = d;
    } else {
        int idx = (b - 256) * 256 + tid;
        int stride = 64 * 256;
        for (int e = idx; e < E_N; e += stride) {
            int bc = batch[e];
            int bp = (e == 0) ? -1 : batch[e - 1];
            for (int g = bp + 1; g <= bc; ++g) d_seg[g] = e;
            if (e == E_N - 1)
                for (int g = bc + 1; g <= G_N; ++g) d_seg[g] = E_N;
        }
    }
}

// ---------------- K3: dominant streaming pass, depth-2 prefetch --------------
#define K3_BLOCK 256
#define K3_GRID  592
#define K3_WARPS (K3_GRID * (K3_BLOCK / 32))

__global__ __launch_bounds__(K3_BLOCK) void k3_edges(
        const float* __restrict__ tok,
        const int* __restrict__ batch,
        const int* __restrict__ sel) {
    int warp = (blockIdx.x * blockDim.x + threadIdx.x) >> 5;
    int lane = threadIdx.x & 31;
    const int chunk = (E_N + K3_WARPS - 1) / K3_WARPS;
    int e0 = warp * chunk;
    int e1 = min(e0 + chunk, E_N);
    if (e0 >= e1) return;

    float4 v0 = ((const float4*)d_v_edge)[lane];
    float4 v1 = ((const float4*)d_v_edge)[lane + 32];

    float4 a0 = make_float4(0.f, 0.f, 0.f, 0.f);
    float4 a1 = make_float4(0.f, 0.f, 0.f, 0.f);
    float keep = 0.f;

    const float4* base = (const float4*)tok;
    float4 t0 = __ldcs(base + (size_t)e0 * 64 + lane);
    float4 t1 = __ldcs(base + (size_t)e0 * 64 + 32 + lane);
    int gt = batch[e0];
    float4 u0 = t0, u1 = t1;
    int gu = gt;
    if (e0 + 1 < e1) {
        u0 = __ldcs(base + (size_t)(e0 + 1) * 64 + lane);
        u1 = __ldcs(base + (size_t)(e0 + 1) * 64 + 32 + lane);
        gu = batch[e0 + 1];
    }
    int cg = gt;

    for (int e = e0; e < e1; ++e) {
        float4 p0 = u0, p1 = u1; int gp = gu;
        if (e + 2 < e1) {
            p0 = __ldcs(base + (size_t)(e + 2) * 64 + lane);
            p1 = __ldcs(base + (size_t)(e + 2) * 64 + 32 + lane);
            gp = batch[e + 2];
        }
        if (gt != cg) {  // segment boundary: flush partial sums
            float* dst = d_sum_tok + (size_t)cg * H_N;
            atomicAdd(&dst[4 * lane + 0], a0.x);
            atomicAdd(&dst[4 * lane + 1], a0.y);
            atomicAdd(&dst[4 * lane + 2], a0.z);
            atomicAdd(&dst[4 * lane + 3], a0.w);
            atomicAdd(&dst[128 + 4 * lane + 0], a1.x);
            atomicAdd(&dst[128 + 4 * lane + 1], a1.y);
            atomicAdd(&dst[128 + 4 * lane + 2], a1.z);
            atomicAdd(&dst[128 + 4 * lane + 3], a1.w);
            a0 = make_float4(0.f, 0.f, 0.f, 0.f);
            a1 = make_float4(0.f, 0.f, 0.f, 0.f);
            cg = gt;
        }
        a0.x += t0.x; a0.y += t0.y; a0.z += t0.z; a0.w += t0.w;
        a1.x += t1.x; a1.y += t1.y; a1.z += t1.z; a1.w += t1.w;

        float d = t0.x * v0.x;
        d = fmaf(t0.y, v0.y, d); d = fmaf(t0.z, v0.z, d); d = fmaf(t0.w, v0.w, d);
        d = fmaf(t1.x, v1.x, d); d = fmaf(t1.y, v1.y, d);
        d = fmaf(t1.z, v1.z, d); d = fmaf(t1.w, v1.w, d);
        float tot = warp_sum(d);

        float att = tot + d_q_att[gt];
        att = att > 0.f ? att : 0.2f * att;             // LeakyReLU(0.2)
        if (sel[e] == 0) att += 0.5f;                   // frontier bonus
        if (lane == (e & 31)) keep = att;

        if ((e & 31) == 31 || e == e1 - 1) {            // coalesced 128B store
            int bse = e & ~31;
            int idx = bse + lane;
            if (idx >= e0 && idx <= e)
                d_att_raw[idx] = keep;
        }

        t0 = u0; t1 = u1; gt = gu;
        u0 = p0; u1 = p1; gu = gp;
    }
    float* dst = d_sum_tok + (size_t)cg * H_N;
    atomicAdd(&dst[4 * lane + 0], a0.x);
    atomicAdd(&dst[4 * lane + 1], a0.y);
    atomicAdd(&dst[4 * lane + 2], a0.z);
    atomicAdd(&dst[4 * lane + 3], a0.w);
    atomicAdd(&dst[128 + 4 * lane + 0], a1.x);
    atomicAdd(&dst[128 + 4 * lane + 1], a1.y);
    atomicAdd(&dst[128 + 4 * lane + 2], a1.z);
    atomicAdd(&dst[128 + 4 * lane + 3], a1.w);
}

// ---------------- K_TAIL: softmax role + (pool GEMM + LN + MLP + stop) role --
// grid 320 x 512 thr: blocks 0-255 -> softmax/logits; 256-319 -> 4 graphs each.
__global__ __launch_bounds__(512) void k_tail(
        const int* __restrict__ sel,
        const float* __restrict__ q,
        const float* __restrict__ ln_g,
        const float* __restrict__ ln_b,
        const float* __restrict__ b1,
        const float* __restrict__ W2,
        const float* __restrict__ b2,
        float* __restrict__ out_edge,
        float* __restrict__ out_pool,
        float* __restrict__ out_stop) {
    int tid = threadIdx.x;
    int lane = tid & 31, wid = tid >> 5;   // 16 warps

    if (blockIdx.x < 256) {
        // ================= role A: segment softmax + edge logits =============
        int gi = blockIdx.x;
        int start = d_seg[gi], end = d_seg[gi + 1];
        int n = end - start;

        __shared__ float wred[16];
        __shared__ float bcast;
        __shared__ float satt[SEG_CAP];
        __shared__ unsigned char smsk[SEG_CAP];

        if (n <= SEG_CAP) {
            #pragma unroll 4
            for (int i = tid; i < n; i += 512) {
                satt[i] = d_att_raw[start + i];
                smsk[i] = (unsigned char)(sel[start + i] != 0);
            }
            __syncthreads();

            float mx = -INFINITY;
            #pragma unroll 4
            for (int i = tid; i < n; i += 512) mx = fmaxf(mx, satt[i]);
            mx = warp_max(mx);
            if (lane == 0) wred[wid] = mx;
            __syncthreads();
            if (wid == 0) {
                float v = (lane < 16) ? wred[lane] : -INFINITY;
                v = warp_max(v);
                if (lane == 0) bcast = v;
            }
            __syncthreads();
            mx = bcast;

            float sm = 0.f;
            #pragma unroll 4
            for (int i = tid; i < n; i += 512)
                if (!smsk[i]) sm += expf(satt[i] - mx);
            sm = warp_sum(sm);
            if (lane == 0) wred[wid] = sm;
            __syncthreads();
            if (wid == 0) {
                float v = (lane < 16) ? wred[lane] : 0.f;
                v = warp_sum(v);
                if (lane == 0) bcast = mx + logf(fmaxf(v, EPS_F));
            }
            __syncthreads();
            float sub = bcast;

            #pragma unroll 4
            for (int i = tid; i < n; i += 512) {
                float v = LOG_EPS;
                if (!smsk[i]) v = fmaxf(satt[i] - sub, LOG_EPS);
                out_edge[start + i] = v;
            }
        } else {
            float mx = -INFINITY;
            for (int e = start + tid; e < end; e += 512) mx = fmaxf(mx, d_att_raw[e]);
            mx = warp_max(mx);
            if (lane == 0) wred[wid] = mx;
            __syncthreads();
            if (wid == 0) {
                float v = (lane < 16) ? wred[lane] : -INFINITY;
                v = warp_max(v);
                if (lane == 0) bcast = v;
            }
            __syncthreads();
            mx = bcast;

            float sm = 0.f;
            for (int e = start + tid; e < end; e += 512)
                if (sel[e] == 0) sm += expf(d_att_raw[e] - mx);
            sm = warp_sum(sm);
            if (lane == 0) wred[wid] = sm;
            __syncthreads();
            if (wid == 0) {
                float v = (lane < 16) ? wred[lane] : 0.f;
                v = warp_sum(v);
                if (lane == 0) bcast = mx + logf(fmaxf(v, EPS_F));
            }
            __syncthreads();
            float sub = bcast;

            for (int e = start + tid; e < end; e += 512) {
                float v = LOG_EPS;
                if (sel[e] == 0) v = fmaxf(d_att_raw[e] - sub, LOG_EPS);
                out_edge[e] = v;
            }
        }
    } else {
        // ============ role B: 4 graphs: pool GEMM + LN + MLP + stop ==========
        int rb = blockIdx.x - 256;          // 0..63
        int g0 = rb * 4;
        int j = tid & 255, kh = tid >> 8;   // kh in {0,1}

        __shared__ float stok[4][H_N];      // 4 KB
        __shared__ float spart[2][4][H_N];  // 8 KB (GEMM partials)
        __shared__ float sxn[4][H2_N];      // 8 KB
        __shared__ float sred[16];
        __shared__ float bc[2];

        // load 4 sum_tok rows
        #pragma unroll
        for (int i = tid; i < 4 * H_N; i += 512)
            stok[i >> 8][i & 255] = d_sum_tok[(size_t)g0 * H_N + i];
        __syncthreads();

        // ---- GEMM1: pooled partials, k-split across kh ----
        {
            float ac0 = 0.f, ac1 = 0.f, ac2 = 0.f, ac3 = 0.f;
            int kb = kh * 128;
            #pragma unroll 8
            for (int k = kb; k < kb + 128; ++k) {
                float w = d_WeT[k * H_N + j];
                ac0 = fmaf(stok[0][k], w, ac0);
                ac1 = fmaf(stok[1][k], w, ac1);
                ac2 = fmaf(stok[2][k], w, ac2);
                ac3 = fmaf(stok[3][k], w, ac3);
            }
            spart[kh][0][j] = ac0;
            spart[kh][1][j] = ac1;
            spart[kh][2][j] = ac2;
            spart[kh][3][j] = ac3;
        }
        __syncthreads();

        // ---- per-graph: pooled, LayerNorm -> sxn ----
        #pragma unroll
        for (int gg = 0; gg < 4; ++gg) {
            int g = g0 + gg;
            float invden = 1.0f / (float)max(d_seg[g + 1] - d_seg[g], 1);
            float pooled = (spart[0][gg][j] + spart[1][gg][j]) * invden;
            float x1 = q[(size_t)g * H_N + j];

            float v = kh ? (pooled * pooled + x1 * x1) : (pooled + x1);
            v = warp_sum(v);
            if (lane == 0) sred[wid] = v;
            __syncthreads();
            if (wid == 0) {
                float t = (lane < 8) ? sred[lane] : 0.f;
                t = warp_sum(t);
                if (lane == 0) bc[0] = t * (1.0f / 512.0f);
            }
            if (wid == 1) {
                float t = (lane < 8) ? sred[8 + lane] : 0.f;
                t = warp_sum(t);
                if (lane == 0) bc[1] = t * (1.0f / 512.0f);
            }
            __syncthreads();
            float mu = bc[0];
            float var = bc[1] - mu * mu;
            float inv = rsqrtf(var + 1e-5f);
            if (kh == 0) {
                sxn[gg][j] = (pooled - mu) * inv * ln_g[j] + ln_b[j];
                out_pool[(size_t)g * H_N + j] = pooled;
            } else {
                sxn[gg][256 + j] = (x1 - mu) * inv * ln_g[256 + j] + ln_b[256 + j];
            }
            __syncthreads();
        }

        // ---- GEMM2: h1 partials, k-split across kh (K=512) ----
        {
            float ac0 = 0.f, ac1 = 0.f, ac2 = 0.f, ac3 = 0.f;
            int kb = kh * 256;
            #pragma unroll 8
            for (int k = kb; k < kb + 256; ++k) {
                float w = d_W1T[k * H_N + j];
                ac0 = fmaf(sxn[0][k], w, ac0);
                ac1 = fmaf(sxn[1][k], w, ac1);
                ac2 = fmaf(sxn[2][k], w, ac2);
                ac3 = fmaf(sxn[3][k], w, ac3);
            }
            spart[kh][0][j] = ac0;
            spart[kh][1][j] = ac1;
            spart[kh][2][j] = ac2;
            spart[kh][3][j] = ac3;
        }
        __syncthreads();

        // ---- per-graph: GELU + stop dot ----
        #pragma unroll
        for (int gg = 0; gg < 4; ++gg) {
            int g = g0 + gg;
            float x = spart[0][gg][j] + spart[1][gg][j] + b1[j];
            float h = 0.5f * x * (1.0f + erff(x * 0.70710678118654752f));
            float v = kh ? 0.f : h * W2[j];
            v = warp_sum(v);
            if (lane == 0) sred[wid] = v;
            __syncthreads();
            if (wid == 0) {
                float t = (lane < 8) ? sred[lane] : 0.f;
                t = warp_sum(t);
                if (lane == 0) out_stop[g] = t + b2[0];
            }
            __syncthreads();
        }
    }
}

// ---------------- launch -----------------------------------------------------
extern "C" void kernel_launch(void* const* d_in, const int* in_sizes, int n_in,
                              void* d_out, int out_size) {
    const float* edge_tokens     = (const float*)d_in[0];
    const float* question_tokens = (const float*)d_in[1];
    const int*   edge_batch      = (const int*)d_in[2];
    const int*   selected_mask   = (const int*)d_in[3];   // bool promoted to int32
    const float* W_edge          = (const float*)d_in[4];
    const float* W_query         = (const float*)d_in[5];
    const float* att_vec         = (const float*)d_in[6];
    const float* ln_g            = (const float*)d_in[7];
    const float* ln_b            = (const float*)d_in[8];
    const float* W1              = (const float*)d_in[9];
    const float* b1              = (const float*)d_in[10];
    const float* W2              = (const float*)d_in[11];
    const float* b2              = (const float*)d_in[12];

    float* out         = (float*)d_out;
    float* out_edge    = out;                 // [E]
    float* out_stop    = out + E_N;           // [G]
    float* out_pooled  = out + E_N + G_N;     // [G, H]

    kAB_prep<<<320, 256>>>(W_edge, W_query, W1, att_vec,
                           question_tokens, edge_batch);
    k3_edges<<<K3_GRID, K3_BLOCK>>>(edge_tokens, edge_batch, selected_mask);
    k_tail<<<320, 512>>>(selected_mask, question_tokens, ln_g, ln_b,
                         b1, W2, b2, out_edge, out_pooled, out_stop);
}